// round 1
// baseline (speedup 1.0000x reference)
#include <cuda_runtime.h>
#include <cuda_bf16.h>

// Problem constants
#define TT 512
#define BB 64
#define DD 1024
#define HH 1024
#define NBLK 128          // persistent scan blocks (<= 148 SMs, co-resident)
#define NSPLIT 4          // K-split in recurrent GEMM
#define CTILE 32          // columns per scan block

// Scratch (device globals: no allocation allowed)
__device__ float    g_part[NSPLIT][BB * HH];   // split-K partials, 1 MB
__device__ unsigned g_bar[2 * TT];             // one counter per (step, phase)

// ---------------------------------------------------------------------------
// Init: zero barrier counters every launch (replay-deterministic)
// ---------------------------------------------------------------------------
__global__ void init_kernel() {
    int i = blockIdx.x * blockDim.x + threadIdx.x;
    if (i < 2 * TT) g_bar[i] = 0u;
}

// ---------------------------------------------------------------------------
// Kernel 1: xproj = inputs @ W_xh + b  ->  written into d_out[0 : T*B*H]
// Tiled SGEMM: BM=128, BN=64, BK=16, 256 threads, 8x4 microtile
// ---------------------------------------------------------------------------
__global__ __launch_bounds__(256) void xproj_kernel(
    const float* __restrict__ A,      // [32768, 1024]
    const float* __restrict__ W,      // [1024, 1024]
    const float* __restrict__ bias,   // [1024]
    float* __restrict__ out)          // [32768, 1024]
{
    __shared__ float As[16][128];     // transposed: As[k][m]
    __shared__ float Bs[16][64];      // Bs[k][n]

    const int bm  = blockIdx.y * 128;
    const int bn  = blockIdx.x * 64;
    const int tid = threadIdx.x;
    const int tx  = tid & 15;         // col group (4 cols)
    const int ty  = tid >> 4;         // row group (8 rows)

    float acc[8][4];
#pragma unroll
    for (int i = 0; i < 8; i++)
#pragma unroll
        for (int j = 0; j < 4; j++) acc[i][j] = 0.f;

    const int r_ld  = tid >> 1;          // A row this thread loads (0..127)
    const int kq_ld = (tid & 1) * 2;     // first float4 of the row (loads 2)
    const int kk_ld = tid >> 4;          // B tile row
    const int cq_ld = tid & 15;          // B tile float4 col

    for (int k0 = 0; k0 < DD; k0 += 16) {
        // Load A tile (128x16), transpose into As[k][m]
#pragma unroll
        for (int i = 0; i < 2; i++) {
            float4 v = *(const float4*)&A[(size_t)(bm + r_ld) * DD + k0 + (kq_ld + i) * 4];
            As[(kq_ld + i) * 4 + 0][r_ld] = v.x;
            As[(kq_ld + i) * 4 + 1][r_ld] = v.y;
            As[(kq_ld + i) * 4 + 2][r_ld] = v.z;
            As[(kq_ld + i) * 4 + 3][r_ld] = v.w;
        }
        // Load B tile (16x64)
        {
            float4 v = *(const float4*)&W[(size_t)(k0 + kk_ld) * HH + bn + cq_ld * 4];
            *(float4*)&Bs[kk_ld][cq_ld * 4] = v;
        }
        __syncthreads();

#pragma unroll
        for (int kk = 0; kk < 16; kk++) {
            float4 a0 = *(const float4*)&As[kk][ty * 8];
            float4 a1 = *(const float4*)&As[kk][ty * 8 + 4];
            float4 b  = *(const float4*)&Bs[kk][tx * 4];
            float av[8] = {a0.x, a0.y, a0.z, a0.w, a1.x, a1.y, a1.z, a1.w};
            float bv[4] = {b.x, b.y, b.z, b.w};
#pragma unroll
            for (int i = 0; i < 8; i++)
#pragma unroll
                for (int j = 0; j < 4; j++)
                    acc[i][j] += av[i] * bv[j];
        }
        __syncthreads();
    }

    float4 bv;
    bv.x = bias[bn + tx * 4 + 0];
    bv.y = bias[bn + tx * 4 + 1];
    bv.z = bias[bn + tx * 4 + 2];
    bv.w = bias[bn + tx * 4 + 3];
#pragma unroll
    for (int i = 0; i < 8; i++) {
        int row = bm + ty * 8 + i;
        float4 o;
        o.x = acc[i][0] + bv.x;
        o.y = acc[i][1] + bv.y;
        o.z = acc[i][2] + bv.z;
        o.w = acc[i][3] + bv.w;
        *(float4*)&out[(size_t)row * HH + bn + tx * 4] = o;
    }
}

// ---------------------------------------------------------------------------
// Global barrier (persistent kernel, NBLK blocks, fresh counter per slot)
// ---------------------------------------------------------------------------
__device__ __forceinline__ void gbar(int slot) {
    __syncthreads();
    if (threadIdx.x == 0) {
        __threadfence();                       // release our writes
        atomicAdd(&g_bar[slot], 1u);
        volatile unsigned* p = &g_bar[slot];
        while (*p < (unsigned)NBLK) { }
    }
    __syncthreads();
    __threadfence();                           // acquire others' writes
}

// ---------------------------------------------------------------------------
// Kernel 2: persistent scan.
//   h_t = tanh(xp_t + h_{t-1} @ W_hh)
// Block bid: s = bid/32 (K-split slice of 256), ct = bid%32 (32-col tile).
// W_hh slice (256x32 = 32 KB) stays in SMEM for all 512 steps.
// h_{t-1} is read from d_out[t-1] (in-place: xp_t region becomes h_t).
// Phase 1 writes split-K partials; Phase 2 reduces + tanh; 2 barriers/step.
// ---------------------------------------------------------------------------
__global__ __launch_bounds__(256) void scan_kernel(
    const float* __restrict__ state,   // [64, 1024] initial h
    const float* __restrict__ Whh,     // [1024, 1024]
    float* __restrict__ out,           // d_out
    int write_final)
{
    __shared__ float wsm[256][CTILE];  // W_hh[s*256 + k][ct*32 + c]
    __shared__ float hst[32][68];      // transposed h chunk: hst[k][r], padded

    const int bid = blockIdx.x;
    const int tid = threadIdx.x;
    const int s   = bid >> 5;          // 0..3
    const int ct  = bid & 31;          // 0..31

    // Load this block's W slice once (stationary for all 512 steps)
    for (int i = tid; i < 256 * CTILE; i += 256) {
        int k = i >> 5, c = i & 31;
        wsm[k][c] = Whh[(size_t)(s * 256 + k) * HH + ct * CTILE + c];
    }

    const int lane_c = tid & 31;       // column within tile (lane-major!)
    const int rg     = tid >> 5;       // row group: rows rg*8 .. rg*8+7
    const int p2base = bid * 512;      // phase-2 slice

    for (int t = 0; t < TT; t++) {
        const float* hsrc = (t == 0) ? state : (out + (size_t)(t - 1) * BB * HH);

        float acc[8];
#pragma unroll
        for (int i = 0; i < 8; i++) acc[i] = 0.f;

        for (int kc = 0; kc < 256; kc += 32) {
            __syncthreads();   // protect hst reuse
            // stage h[0..63][s*256+kc .. +32] transposed (bypass L1: cross-block data)
            for (int i = tid; i < 512; i += 256) {
                int r  = i >> 3;       // 8 float4 per row
                int k4 = i & 7;
                float4 v = __ldcg((const float4*)&hsrc[(size_t)r * HH + s * 256 + kc + k4 * 4]);
                hst[k4 * 4 + 0][r] = v.x;
                hst[k4 * 4 + 1][r] = v.y;
                hst[k4 * 4 + 2][r] = v.z;
                hst[k4 * 4 + 3][r] = v.w;
            }
            __syncthreads();
#pragma unroll
            for (int k = 0; k < 32; k++) {
                float w = wsm[kc + k][lane_c];                     // conflict-free
                float4 h0 = *(const float4*)&hst[k][rg * 8];       // warp-uniform (bcast)
                float4 h1 = *(const float4*)&hst[k][rg * 8 + 4];   // warp-uniform (bcast)
                acc[0] += h0.x * w; acc[1] += h0.y * w;
                acc[2] += h0.z * w; acc[3] += h0.w * w;
                acc[4] += h1.x * w; acc[5] += h1.y * w;
                acc[6] += h1.z * w; acc[7] += h1.w * w;
            }
        }
        // write split-K partials (coalesced across lanes)
#pragma unroll
        for (int i = 0; i < 8; i++)
            g_part[s][(size_t)(rg * 8 + i) * HH + ct * CTILE + lane_c] = acc[i];

        gbar(2 * t);

        // Phase 2: reduce partials + xp, tanh, write h_t (in place over xp_t)
#pragma unroll
        for (int j = 0; j < 2; j++) {
            int idx = p2base + j * 256 + tid;
            float v = out[(size_t)t * BB * HH + idx]               // xp (this-launch write, L1-safe)
                    + __ldcg(&g_part[0][idx]) + __ldcg(&g_part[1][idx])
                    + __ldcg(&g_part[2][idx]) + __ldcg(&g_part[3][idx]);
            float h = tanhf(v);
            out[(size_t)t * BB * HH + idx] = h;
            if (write_final && t == TT - 1)
                out[(size_t)TT * BB * HH + idx] = h;   // final_state
        }

        gbar(2 * t + 1);
    }
}

// ---------------------------------------------------------------------------
extern "C" void kernel_launch(void* const* d_in, const int* in_sizes, int n_in,
                              void* d_out, int out_size) {
    const float* inputs = (const float*)d_in[0];   // [T,B,D]
    const float* state  = (const float*)d_in[1];   // [B,H]
    const float* W_xh   = (const float*)d_in[2];   // [D,H]
    const float* W_hh   = (const float*)d_in[3];   // [H,H]
    const float* b_h    = (const float*)d_in[4];   // [H]
    float* out = (float*)d_out;

    int write_final = (out_size >= TT * BB * HH + BB * HH) ? 1 : 0;

    init_kernel<<<4, 256>>>();

    dim3 g1(HH / 64, (TT * BB) / 128);
    xproj_kernel<<<g1, 256>>>(inputs, W_xh, b_h, out);

    scan_kernel<<<NBLK, 256>>>(state, W_hh, out, write_final);
}

// round 2
// speedup vs baseline: 1.4725x; 1.4725x over previous
#include <cuda_runtime.h>
#include <cuda_bf16.h>

// Problem constants
#define TT 512
#define BB 64
#define DD 1024
#define HH 1024
#define NBLK 128          // persistent scan blocks (<= 148 SMs, co-resident)

// hst layout: [buf:2][kslice:4][k:32] rows of 16 floats, padded stride 20
#define HSTRIDE 20
#define HST_PER_BUF (4 * 32 * HSTRIDE)      // 2560 floats
#define SM_W_FLOATS (1024 * 32)             // 32768
#define SM_HST_OFF  SM_W_FLOATS             // 32768
#define SM_RED_OFF  (SM_W_FLOATS + 2 * HST_PER_BUF)   // 37888
#define SM_TOTAL_FLOATS (SM_RED_OFF + 4 * 512)        // 39936
#define SM_TOTAL_BYTES  (SM_TOTAL_FLOATS * 4)         // 159744

// Scratch (device globals: no allocation allowed)
__device__ unsigned g_bar[TT];               // one counter per step

// ---------------------------------------------------------------------------
// Init: zero barrier counters every launch (replay-deterministic)
// ---------------------------------------------------------------------------
__global__ void init_kernel() {
    int i = blockIdx.x * blockDim.x + threadIdx.x;
    if (i < TT) g_bar[i] = 0u;
}

// ---------------------------------------------------------------------------
// Kernel 1: xproj = inputs @ W_xh + b  ->  written into d_out[0 : T*B*H]
// Tiled SGEMM: BM=128, BN=64, BK=16, 256 threads, 8x4 microtile (FFMA floor)
// ---------------------------------------------------------------------------
__global__ __launch_bounds__(256) void xproj_kernel(
    const float* __restrict__ A,      // [32768, 1024]
    const float* __restrict__ W,      // [1024, 1024]
    const float* __restrict__ bias,   // [1024]
    float* __restrict__ out)          // [32768, 1024]
{
    __shared__ float As[16][128];     // transposed: As[k][m]
    __shared__ float Bs[16][64];      // Bs[k][n]

    const int bm  = blockIdx.y * 128;
    const int bn  = blockIdx.x * 64;
    const int tid = threadIdx.x;
    const int tx  = tid & 15;         // col group (4 cols)
    const int ty  = tid >> 4;         // row group (8 rows)

    float acc[8][4];
#pragma unroll
    for (int i = 0; i < 8; i++)
#pragma unroll
        for (int j = 0; j < 4; j++) acc[i][j] = 0.f;

    const int r_ld  = tid >> 1;          // A row this thread loads (0..127)
    const int kq_ld = (tid & 1) * 2;     // first float4 of the row (loads 2)
    const int kk_ld = tid >> 4;          // B tile row
    const int cq_ld = tid & 15;          // B tile float4 col

    for (int k0 = 0; k0 < DD; k0 += 16) {
#pragma unroll
        for (int i = 0; i < 2; i++) {
            float4 v = *(const float4*)&A[(size_t)(bm + r_ld) * DD + k0 + (kq_ld + i) * 4];
            As[(kq_ld + i) * 4 + 0][r_ld] = v.x;
            As[(kq_ld + i) * 4 + 1][r_ld] = v.y;
            As[(kq_ld + i) * 4 + 2][r_ld] = v.z;
            As[(kq_ld + i) * 4 + 3][r_ld] = v.w;
        }
        {
            float4 v = *(const float4*)&W[(size_t)(k0 + kk_ld) * HH + bn + cq_ld * 4];
            *(float4*)&Bs[kk_ld][cq_ld * 4] = v;
        }
        __syncthreads();

#pragma unroll
        for (int kk = 0; kk < 16; kk++) {
            float4 a0 = *(const float4*)&As[kk][ty * 8];
            float4 a1 = *(const float4*)&As[kk][ty * 8 + 4];
            float4 b  = *(const float4*)&Bs[kk][tx * 4];
            float av[8] = {a0.x, a0.y, a0.z, a0.w, a1.x, a1.y, a1.z, a1.w};
            float bv[4] = {b.x, b.y, b.z, b.w};
#pragma unroll
            for (int i = 0; i < 8; i++)
#pragma unroll
                for (int j = 0; j < 4; j++)
                    acc[i][j] += av[i] * bv[j];
        }
        __syncthreads();
    }

    float4 bv;
    bv.x = bias[bn + tx * 4 + 0];
    bv.y = bias[bn + tx * 4 + 1];
    bv.z = bias[bn + tx * 4 + 2];
    bv.w = bias[bn + tx * 4 + 3];
#pragma unroll
    for (int i = 0; i < 8; i++) {
        int row = bm + ty * 8 + i;
        float4 o;
        o.x = acc[i][0] + bv.x;
        o.y = acc[i][1] + bv.y;
        o.z = acc[i][2] + bv.z;
        o.w = acc[i][3] + bv.w;
        *(float4*)&out[(size_t)row * HH + bn + tx * 4] = o;
    }
}

// ---------------------------------------------------------------------------
// Global barrier: ONE per step now
// ---------------------------------------------------------------------------
__device__ __forceinline__ void gbar(int slot) {
    __syncthreads();
    if (threadIdx.x == 0) {
        __threadfence();                       // release h_t writes
        atomicAdd(&g_bar[slot], 1u);
        volatile unsigned* p = &g_bar[slot];
        while (*p < (unsigned)NBLK) { }
    }
    __syncthreads();
    __threadfence();                           // acquire others' writes
}

// ---------------------------------------------------------------------------
// Kernel 2: persistent scan, full-K per block + intra-block split-K.
//   Block bid: rq = bid>>5 (16-row quad), ct = bid&31 (32-col tile).
//   Warp wid: s = wid&3 (K-slice of 256), rg = wid>>2 (8-row group).
//   W_hh slice [1024][32] (128 KB) SMEM-resident for all 512 steps.
//   ONE global barrier per step, no global partials.
// ---------------------------------------------------------------------------
__global__ __launch_bounds__(256) void scan_kernel(
    const float* __restrict__ state,   // [64, 1024] initial h
    const float* __restrict__ Whh,     // [1024, 1024]
    float* __restrict__ out,           // d_out
    int write_final)
{
    extern __shared__ float sm[];
    float* wsm = sm;                  // [1024][32]
    float* hst = sm + SM_HST_OFF;     // [2][4][32] x stride 20 (16 rows used)
    float* red = sm + SM_RED_OFF;     // [4][512]

    const int bid = blockIdx.x;
    const int tid = threadIdx.x;
    const int rq  = bid >> 5;          // 0..3   rows rq*16 .. +15
    const int ct  = bid & 31;          // 0..31  cols ct*32 .. +31

    const int lane = tid & 31;
    const int wid  = tid >> 5;
    const int s    = wid & 3;          // K-slice: k in [s*256, s*256+256)
    const int rg   = wid >> 2;         // rows rg*8 .. rg*8+7 (within quad)

    // Load W slice once: wsm[k][c] = Whh[k][ct*32+c]
    for (int i = tid; i < 1024 * 32; i += 256) {
        int k = i >> 5, c = i & 31;
        wsm[i] = Whh[(size_t)k * HH + ct * 32 + c];
    }

    // staging-load decomposition (each thread loads 2 float4 per chunk)
    const int l_k4 = tid & 7;           // which float4 along k (0..7 -> 32 k)
    const int l_r  = (tid >> 3) & 15;   // row within quad
    const int l_s0 = tid >> 7;          // slice 0..1 ; second load: +2

    // phase-2 output indices (2 per thread)
    const int o0 = tid, o1 = tid + 256;
    const int gidx0 = (rq * 16 + (o0 >> 5)) * HH + ct * 32 + (o0 & 31);
    const int gidx1 = (rq * 16 + (o1 >> 5)) * HH + ct * 32 + (o1 & 31);

    __syncthreads();

    for (int t = 0; t < TT; t++) {
        const float* hsrc = (t == 0) ? state : (out + (size_t)(t - 1) * BB * HH);
        float* xp = out + (size_t)t * BB * HH;

        // prefetch xp for this step (hides L2/DRAM latency under FMA)
        float xp0 = xp[gidx0];
        float xp1 = xp[gidx1];

        float acc[8];
#pragma unroll
        for (int i = 0; i < 8; i++) acc[i] = 0.f;

        // stage chunk 0 into buf 0
        {
            float4 v0 = __ldcg((const float4*)&hsrc[(size_t)(rq * 16 + l_r) * HH + l_s0 * 256 + l_k4 * 4]);
            float4 v1 = __ldcg((const float4*)&hsrc[(size_t)(rq * 16 + l_r) * HH + (l_s0 + 2) * 256 + l_k4 * 4]);
            float* d0 = &hst[(l_s0 * 32 + l_k4 * 4) * HSTRIDE + l_r];
            d0[0] = v0.x; d0[HSTRIDE] = v0.y; d0[2 * HSTRIDE] = v0.z; d0[3 * HSTRIDE] = v0.w;
            float* d1 = &hst[((l_s0 + 2) * 32 + l_k4 * 4) * HSTRIDE + l_r];
            d1[0] = v1.x; d1[HSTRIDE] = v1.y; d1[2 * HSTRIDE] = v1.z; d1[3 * HSTRIDE] = v1.w;
        }
        __syncthreads();

        int b = 0;
        for (int c = 0; c < 8; c++) {
            float4 v0, v1;
            if (c < 7) {
                v0 = __ldcg((const float4*)&hsrc[(size_t)(rq * 16 + l_r) * HH + l_s0 * 256 + (c + 1) * 32 + l_k4 * 4]);
                v1 = __ldcg((const float4*)&hsrc[(size_t)(rq * 16 + l_r) * HH + (l_s0 + 2) * 256 + (c + 1) * 32 + l_k4 * 4]);
            }

            const float* wbase = &wsm[(s * 256 + c * 32) * 32 + lane];
            const float* hbase = &hst[b * HST_PER_BUF + (s * 32) * HSTRIDE + rg * 8];
#pragma unroll
            for (int k = 0; k < 32; k++) {
                float  w  = wbase[k * 32];                         // conflict-free
                float4 h0 = *(const float4*)&hbase[k * HSTRIDE];   // warp-uniform bcast
                float4 h1 = *(const float4*)&hbase[k * HSTRIDE + 4];
                acc[0] += h0.x * w; acc[1] += h0.y * w;
                acc[2] += h0.z * w; acc[3] += h0.w * w;
                acc[4] += h1.x * w; acc[5] += h1.y * w;
                acc[6] += h1.z * w; acc[7] += h1.w * w;
            }

            if (c < 7) {
                float* d0 = &hst[(b ^ 1) * HST_PER_BUF + (l_s0 * 32 + l_k4 * 4) * HSTRIDE + l_r];
                d0[0] = v0.x; d0[HSTRIDE] = v0.y; d0[2 * HSTRIDE] = v0.z; d0[3 * HSTRIDE] = v0.w;
                float* d1 = &hst[(b ^ 1) * HST_PER_BUF + ((l_s0 + 2) * 32 + l_k4 * 4) * HSTRIDE + l_r];
                d1[0] = v1.x; d1[HSTRIDE] = v1.y; d1[2 * HSTRIDE] = v1.z; d1[3 * HSTRIDE] = v1.w;
            }
            __syncthreads();
            b ^= 1;
        }

        // intra-block split-K reduction: red[s][(rg*8+i)*32 + lane]
#pragma unroll
        for (int i = 0; i < 8; i++)
            red[s * 512 + (rg * 8 + i) * 32 + lane] = acc[i];
        __syncthreads();

        // phase 2: sum 4 slices + xp, tanh, write h_t (in place over xp_t)
        {
            float v0 = red[o0] + red[512 + o0] + red[1024 + o0] + red[1536 + o0] + xp0;
            float v1 = red[o1] + red[512 + o1] + red[1024 + o1] + red[1536 + o1] + xp1;
            float h0 = tanhf(v0);
            float h1 = tanhf(v1);
            xp[gidx0] = h0;
            xp[gidx1] = h1;
            if (write_final && t == TT - 1) {
                out[(size_t)TT * BB * HH + gidx0] = h0;
                out[(size_t)TT * BB * HH + gidx1] = h1;
            }
        }

        gbar(t);   // single barrier per step
    }
}

// ---------------------------------------------------------------------------
extern "C" void kernel_launch(void* const* d_in, const int* in_sizes, int n_in,
                              void* d_out, int out_size) {
    const float* inputs = (const float*)d_in[0];   // [T,B,D]
    const float* state  = (const float*)d_in[1];   // [B,H]
    const float* W_xh   = (const float*)d_in[2];   // [D,H]
    const float* W_hh   = (const float*)d_in[3];   // [H,H]
    const float* b_h    = (const float*)d_in[4];   // [H]
    float* out = (float*)d_out;

    int write_final = (out_size >= TT * BB * HH + BB * HH) ? 1 : 0;

    static int smem_set = 0;
    if (!smem_set) {
        cudaFuncSetAttribute(scan_kernel,
                             cudaFuncAttributeMaxDynamicSharedMemorySize,
                             SM_TOTAL_BYTES);
        smem_set = 1;
    }

    init_kernel<<<2, 256>>>();

    dim3 g1(HH / 64, (TT * BB) / 128);
    xproj_kernel<<<g1, 256>>>(inputs, W_xh, b_h, out);

    scan_kernel<<<NBLK, 256, SM_TOTAL_BYTES>>>(state, W_hh, out, write_final);
}